// round 4
// baseline (speedup 1.0000x reference)
#include <cuda_runtime.h>
#include <math.h>

#define NN   512
#define CSd  384
#define CZd  128
#define Hd   12
#define Cd   16
#define PQd  4
#define PVd  8
#define DE   28
#define CATd 2017
#define MPROJ 1152
#define KSPLIT 8

typedef unsigned long long ull;

// ---------------- packed f32x2 helpers ----------------
__device__ __forceinline__ void ffma2(ull& acc, ull a, ull b) {
    asm("fma.rn.f32x2 %0, %1, %2, %0;" : "+l"(acc) : "l"(a), "l"(b));
}
__device__ __forceinline__ ull pk2(float x, float y) {
    ull r; asm("mov.b64 %0, {%1,%2};" : "=l"(r) : "f"(x), "f"(y)); return r;
}
__device__ __forceinline__ void upk2(ull v, float& x, float& y) {
    asm("mov.b64 {%0,%1}, %2;" : "=f"(x), "=f"(y) : "l"(v));
}

// ---------------- device scratch ----------------
__device__ float g_Wcat[MPROJ * CSd];
__device__ float g_P[MPROJ * NN];
__device__ float g_qe[Hd * DE * NN];
__device__ float g_ke[Hd * DE * NN];
__device__ float g_qn[Hd * NN];
__device__ float g_kn[Hd * NN];
__device__ float g_vr[Hd * Cd * NN];
__device__ float g_vg[3 * Hd * PVd * NN];
__device__ float g_A[NN * Hd * NN];          // probs [i][h][j]
__device__ float g_o3g[288 * NN];            // global-frame o3 [rr][i]
__device__ float g_cat[CATd * NN];
__device__ float g_part[KSPLIT * CSd * NN];

// ---------------- weight concat ----------------
__global__ void concat_w(const float* __restrict__ Wq, const float* __restrict__ Wk,
                         const float* __restrict__ Wv, const float* __restrict__ Wqp,
                         const float* __restrict__ Wkp, const float* __restrict__ Wvp) {
    int idx = blockIdx.x * 256 + threadIdx.x;
    if (idx >= MPROJ * CSd) return;
    int row = idx / CSd, c = idx % CSd;
    float v;
    if      (row < 192) v = Wq [(row      ) * CSd + c];
    else if (row < 384) v = Wk [(row - 192) * CSd + c];
    else if (row < 576) v = Wv [(row - 384) * CSd + c];
    else if (row < 720) v = Wqp[(row - 576) * CSd + c];
    else if (row < 864) v = Wkp[(row - 720) * CSd + c];
    else                v = Wvp[(row - 864) * CSd + c];
    g_Wcat[idx] = v;
}

// ---------------- tiled GEMM with split-K, pre-packed B ----------------
__global__ __launch_bounds__(256) void gemm64(const float* __restrict__ A,
                                              const float* __restrict__ B,
                                              float* __restrict__ C,
                                              int M, int Nc, int K) {
    int nb = blockIdx.x, mb = blockIdx.y, zb = blockIdx.z;
    int Kc = (K + gridDim.z - 1) / gridDim.z;
    int k0 = zb * Kc;
    int kend = min(K, k0 + Kc);

    __shared__ float As[16][64];
    __shared__ ull   Bs2[16][64];   // pre-duplicated (b,b)

    int tid = threadIdx.x;
    int ty = tid >> 4, tx = tid & 15;
    ull acc2[2][4];   // (m-pair, n)
#pragma unroll
    for (int u = 0; u < 2; ++u)
#pragma unroll
        for (int v = 0; v < 4; ++v) acc2[u][v] = 0ull;

    for (int kk = k0; kk < kend; kk += 16) {
#pragma unroll
        for (int l = 0; l < 4; ++l) {
            int e = tid + l * 256;
            int m = e >> 4, k = e & 15;
            As[k][m] = (kk + k < kend) ? A[(size_t)(mb * 64 + m) * K + kk + k] : 0.f;
        }
#pragma unroll
        for (int l = 0; l < 4; ++l) {
            int e = tid + l * 256;
            int k = e >> 6, n = e & 63;
            float v = (kk + k < kend) ? B[(size_t)(kk + k) * Nc + nb * 64 + n] : 0.f;
            Bs2[k][n] = pk2(v, v);
        }
        __syncthreads();
#pragma unroll
        for (int k = 0; k < 16; ++k) {
            const ull* a2 = (const ull*)&As[k][ty * 4];   // (m0,m1) (m2,m3)
            ull a0 = a2[0], a1 = a2[1];
            ull b0 = Bs2[k][tx * 4], b1 = Bs2[k][tx * 4 + 1];
            ull b2 = Bs2[k][tx * 4 + 2], b3 = Bs2[k][tx * 4 + 3];
            ffma2(acc2[0][0], a0, b0); ffma2(acc2[0][1], a0, b1);
            ffma2(acc2[0][2], a0, b2); ffma2(acc2[0][3], a0, b3);
            ffma2(acc2[1][0], a1, b0); ffma2(acc2[1][1], a1, b1);
            ffma2(acc2[1][2], a1, b2); ffma2(acc2[1][3], a1, b3);
        }
        __syncthreads();
    }
    float* Cz = C + (size_t)zb * M * Nc;
#pragma unroll
    for (int u = 0; u < 2; ++u)
#pragma unroll
        for (int v = 0; v < 4; ++v) {
            float lo, hi;
            upk2(acc2[u][v], lo, hi);
            Cz[(size_t)(mb * 64 + ty * 4 + u * 2    ) * Nc + nb * 64 + tx * 4 + v] = lo;
            Cz[(size_t)(mb * 64 + ty * 4 + u * 2 + 1) * Nc + nb * 64 + tx * 4 + v] = hi;
        }
}

// ---------------- prep: parallel over (h, i) ----------------
__global__ void prep_kernel(const float* __restrict__ t_r, const float* __restrict__ t_t,
                            const float* __restrict__ gamma) {
    int idx = blockIdx.x * 256 + threadIdx.x;
    if (idx >= Hd * NN) return;
    int h = idx / NN, i = idx % NN;
    const float w_c = 0.23570226039551584f;
    float R[9], T[3];
#pragma unroll
    for (int r = 0; r < 9; ++r) R[r] = t_r[i * 9 + r];
#pragma unroll
    for (int c = 0; c < 3; ++c) T[c] = t_t[i * 3 + c];

    float x = gamma[h];
    float sp = (x > 20.f) ? x : log1pf(expf(x));
    float g = sp * w_c * 0.5f;

#pragma unroll
    for (int c = 0; c < Cd; ++c) {
        g_qe[(h * DE + c) * NN + i] = g_P[(      c * Hd + h) * NN + i] * 0.25f;
        g_ke[(h * DE + c) * NN + i] = g_P[(192 + c * Hd + h) * NN + i];
    }
    float qn = 0.f, kn = 0.f;
#pragma unroll
    for (int p = 0; p < PQd; ++p) {
        float q0 = g_P[(576 +  0 + h * 4 + p) * NN + i];
        float q1 = g_P[(576 + 48 + h * 4 + p) * NN + i];
        float q2 = g_P[(576 + 96 + h * 4 + p) * NN + i];
        float k0 = g_P[(720 +  0 + h * 4 + p) * NN + i];
        float k1 = g_P[(720 + 48 + h * 4 + p) * NN + i];
        float k2 = g_P[(720 + 96 + h * 4 + p) * NN + i];
#pragma unroll
        for (int co = 0; co < 3; ++co) {
            float qg = R[co * 3] * q0 + R[co * 3 + 1] * q1 + R[co * 3 + 2] * q2 + T[co];
            float kg = R[co * 3] * k0 + R[co * 3 + 1] * k1 + R[co * 3 + 2] * k2 + T[co];
            g_qe[(h * DE + 16 + co * 4 + p) * NN + i] = 2.f * g * qg;
            g_ke[(h * DE + 16 + co * 4 + p) * NN + i] = kg;
            qn += qg * qg;
            kn += kg * kg;
        }
    }
    g_qn[h * NN + i] = g * qn;
    g_kn[h * NN + i] = g * kn;

#pragma unroll
    for (int c = 0; c < Cd; ++c)
        g_vr[(h * Cd + c) * NN + i] = g_P[(384 + c * Hd + h) * NN + i];

#pragma unroll
    for (int p = 0; p < PVd; ++p) {
        float v0 = g_P[(864 +   0 + h * 8 + p) * NN + i];
        float v1 = g_P[(864 +  96 + h * 8 + p) * NN + i];
        float v2 = g_P[(864 + 192 + h * 8 + p) * NN + i];
#pragma unroll
        for (int co = 0; co < 3; ++co)
            g_vg[(co * 96 + h * 8 + p) * NN + i] =
                R[co * 3] * v0 + R[co * 3 + 1] * v1 + R[co * 3 + 2] * v2 + T[co];
    }
}

// ====== fused logits + softmax + o1 : 2 blocks per query row (6 heads each) ======
// smem bytes: S[6][512]f @0 (12288) | W2[128][6]ull @12288 (6144)
//             | QE2[168]ull @18432 (1344) | QN[6]f @19776 (24)
#define FZ_SMEM 19840
#define HH 6

__global__ __launch_bounds__(256, 3) void fusedz_kernel(const float* __restrict__ Z,
                                                        const float* __restrict__ Wb) {
    extern __shared__ char smraw[];
    float* S   = (float*)(smraw);
    ull*   W2  = (ull*)(smraw + 12288);
    ull*   QE2 = (ull*)(smraw + 18432);
    float* QN  = (float*)(smraw + 19776);

    const int tid = threadIdx.x;
    const int i  = blockIdx.x >> 1;
    const int h0 = (blockIdx.x & 1) * HH;
    const float w_l = 0.5773502691896258f;

    for (int t = tid; t < CZd * HH; t += 256) {
        int hh = t % HH, c = t / HH;
        float w = Wb[(h0 + hh) * CZd + c];
        W2[t] = pk2(w, w);
    }
    for (int t = tid; t < HH * DE; t += 256) {
        int hh = t / DE, d = t % DE;
        float v = g_qe[((h0 + hh) * DE + d) * NN + i];
        QE2[t] = pk2(v, v);
    }
    if (tid < HH) QN[tid] = g_qn[(h0 + tid) * NN + i];
    __syncthreads();

    const ull* z64  = (const ull*)Z;
    const ull* ke64 = (const ull*)g_ke;
    const ull* kn64 = (const ull*)g_kn;

    ull acc[HH];
#pragma unroll
    for (int h = 0; h < HH; ++h) acc[h] = 0ull;

    // ---- Phase A: bias = Wb @ z ----
    size_t base = (size_t)i * (NN / 2) + tid;
#pragma unroll 2
    for (int c = 0; c < CZd; c += 4) {
        ull z0 = z64[(size_t)(c    ) * (NN * NN / 2) + base];
        ull z1 = z64[(size_t)(c + 1) * (NN * NN / 2) + base];
        ull z2 = z64[(size_t)(c + 2) * (NN * NN / 2) + base];
        ull z3 = z64[(size_t)(c + 3) * (NN * NN / 2) + base];
#pragma unroll
        for (int h = 0; h < HH; ++h) ffma2(acc[h], W2[(c    ) * HH + h], z0);
#pragma unroll
        for (int h = 0; h < HH; ++h) ffma2(acc[h], W2[(c + 1) * HH + h], z1);
#pragma unroll
        for (int h = 0; h < HH; ++h) ffma2(acc[h], W2[(c + 2) * HH + h], z2);
#pragma unroll
        for (int h = 0; h < HH; ++h) ffma2(acc[h], W2[(c + 3) * HH + h], z3);
    }

    // ---- qk + distance augmented dot ----
#pragma unroll
    for (int h = 0; h < HH; ++h) {
#pragma unroll 4
        for (int d = 0; d < DE; ++d) {
            ull ke2 = ke64[(size_t)((h0 + h) * DE + d) * (NN / 2) + tid];
            ffma2(acc[h], QE2[h * DE + d], ke2);
        }
    }

    // ---- logits into smem ----
    int j0 = 2 * tid;
#pragma unroll
    for (int h = 0; h < HH; ++h) {
        float klo, khi;
        upk2(kn64[(h0 + h) * (NN / 2) + tid], klo, khi);
        float a, b2;
        upk2(acc[h], a, b2);
        S[h * NN + j0]     = w_l * (a  - QN[h] - klo);
        S[h * NN + j0 + 1] = w_l * (b2 - QN[h] - khi);
    }
    __syncthreads();

    // ---- softmax: 6 rows over warps 0..5 ----
    const int warp = tid >> 5, lane = tid & 31;
    if (warp < HH) {
        float* Sr = S + warp * NN;
        float m = -1e30f;
#pragma unroll
        for (int k = 0; k < 16; ++k) m = fmaxf(m, Sr[k * 32 + lane]);
#pragma unroll
        for (int o = 16; o; o >>= 1) m = fmaxf(m, __shfl_xor_sync(0xffffffffu, m, o));
        float ssum = 0.f;
#pragma unroll
        for (int k = 0; k < 16; ++k) {
            float e = __expf(Sr[k * 32 + lane] - m);
            Sr[k * 32 + lane] = e;
            ssum += e;
        }
#pragma unroll
        for (int o = 16; o; o >>= 1) ssum += __shfl_xor_sync(0xffffffffu, ssum, o);
        float inv = 1.f / ssum;
#pragma unroll
        for (int k = 0; k < 16; ++k) Sr[k * 32 + lane] *= inv;
    }
    __syncthreads();

    // ---- export probs ----
    {
        float4* dst = (float4*)(g_A + (size_t)i * Hd * NN + h0 * NN);
        const float4* src = (const float4*)S;
        for (int t = tid; t < HH * NN / 4; t += 256) dst[t] = src[t];
    }

    // ---- Phase B: o1[c,h] (z row now hot in L2) ----
    const ull* A64 = (const ull*)S;
    for (int c = warp; c < CZd; c += 8) {
        ull acc1[HH];
#pragma unroll
        for (int h = 0; h < HH; ++h) acc1[h] = 0ull;
        size_t zb = (size_t)c * (NN * NN / 2) + (size_t)i * (NN / 2);
#pragma unroll
        for (int k = 0; k < 8; ++k) {
            int jp = k * 32 + lane;
            ull z2 = z64[zb + jp];
#pragma unroll
            for (int h = 0; h < HH; ++h)
                ffma2(acc1[h], A64[h * (NN / 2) + jp], z2);
        }
#pragma unroll
        for (int h = 0; h < HH; ++h) {
            float a, b2;
            upk2(acc1[h], a, b2);
            float s = a + b2;
#pragma unroll
            for (int o = 16; o; o >>= 1) s += __shfl_xor_sync(0xffffffffu, s, o);
            if (lane == 0) g_cat[(size_t)(c * Hd + h0 + h) * NN + i] = s;
        }
    }
}

// ---------------- o2 + o3g: 4 query rows per block, rows split over 2 blocks ----------------
#define O23_SMEM 98304

__global__ __launch_bounds__(256) void o23_kernel() {
    extern __shared__ char smraw[];
    float* As = (float*)smraw;

    const int tid = threadIdx.x;
    const int i0 = blockIdx.x * 4;

    {
        float4* d = (float4*)As;
        const float4* s = (const float4*)(g_A + (size_t)i0 * Hd * NN);
        for (int t = tid; t < 4 * Hd * NN / 4; t += 256) d[t] = s[t];
    }
    __syncthreads();

    const ull* A64 = (const ull*)As;
    const int warp = tid >> 5, lane = tid & 31;
    const int rbeg = blockIdx.y * 240;

    for (int r = rbeg + warp; r < rbeg + 240; r += 8) {
        const ull* row64;
        int h, rr = 0;
        if (r < 192) { row64 = (const ull*)(g_vr + (size_t)r * NN); h = r >> 4; }
        else { rr = r - 192; row64 = (const ull*)(g_vg + (size_t)rr * NN); h = (rr % 96) >> 3; }

        ull acc[4];
#pragma unroll
        for (int ii = 0; ii < 4; ++ii) acc[ii] = 0ull;
#pragma unroll
        for (int k = 0; k < 8; ++k) {
            int jp = k * 32 + lane;
            ull v2 = row64[jp];
#pragma unroll
            for (int ii = 0; ii < 4; ++ii)
                ffma2(acc[ii], A64[ii * (Hd * NN / 2) + h * (NN / 2) + jp], v2);
        }
#pragma unroll
        for (int ii = 0; ii < 4; ++ii) {
            float a, b2;
            upk2(acc[ii], a, b2);
            float s = a + b2;
#pragma unroll
            for (int o = 16; o; o >>= 1) s += __shfl_xor_sync(0xffffffffu, s, o);
            if (lane == 0) {
                if (r < 192) g_cat[(size_t)(1536 + (r & 15) * Hd + h) * NN + i0 + ii] = s;
                else         g_o3g[(size_t)rr * NN + i0 + ii] = s;
            }
        }
    }
}

// ---------------- o3 inverse transform + norm (per i) ----------------
__global__ void o3fix_kernel(const float* __restrict__ t_r, const float* __restrict__ t_t) {
    int i = blockIdx.x * 256 + threadIdx.x;
    if (i >= NN) return;
    float R[9], T[3];
#pragma unroll
    for (int r = 0; r < 9; ++r) R[r] = t_r[i * 9 + r];
#pragma unroll
    for (int c = 0; c < 3; ++c) T[c] = t_t[i * 3 + c];

    float nrm = 0.f;
    for (int hp = 0; hp < 96; ++hp) {
        float a0 = g_o3g[(size_t)(0 * 96 + hp) * NN + i] - T[0];
        float a1 = g_o3g[(size_t)(1 * 96 + hp) * NN + i] - T[1];
        float a2 = g_o3g[(size_t)(2 * 96 + hp) * NN + i] - T[2];
#pragma unroll
        for (int co = 0; co < 3; ++co) {
            float v = R[co] * a0 + R[3 + co] * a1 + R[6 + co] * a2;
            g_cat[(size_t)(1728 + co * 96 + hp) * NN + i] = v;
            nrm += v * v;
        }
    }
    g_cat[(size_t)2016 * NN + i] = sqrtf(nrm);
}

// ---------------- final reduce ----------------
__global__ void reduce_out(const float* __restrict__ bs, float* __restrict__ out) {
    int idx = blockIdx.x * 256 + threadIdx.x;
    if (idx >= CSd * NN) return;
    int o = idx >> 9;
    float v = bs[o];
#pragma unroll
    for (int zk = 0; zk < KSPLIT; ++zk) v += g_part[(size_t)zk * CSd * NN + idx];
    out[idx] = v;
}

// ---------------- launcher ----------------
extern "C" void kernel_launch(void* const* d_in, const int* in_sizes, int n_in,
                              void* d_out, int out_size) {
    const float* s    = (const float*)d_in[0];
    const float* z    = (const float*)d_in[1];
    const float* t_r  = (const float*)d_in[2];
    const float* t_t  = (const float*)d_in[3];
    const float* Wq   = (const float*)d_in[4];
    const float* Wk   = (const float*)d_in[5];
    const float* Wv   = (const float*)d_in[6];
    const float* Wqp  = (const float*)d_in[7];
    const float* Wkp  = (const float*)d_in[8];
    const float* Wvp  = (const float*)d_in[9];
    const float* Wb   = (const float*)d_in[10];
    const float* gam  = (const float*)d_in[11];
    const float* Ws   = (const float*)d_in[12];
    const float* bs   = (const float*)d_in[13];
    float* out = (float*)d_out;

    float *pWcat, *pP, *pCat, *pPart;
    cudaGetSymbolAddress((void**)&pWcat, g_Wcat);
    cudaGetSymbolAddress((void**)&pP,    g_P);
    cudaGetSymbolAddress((void**)&pCat,  g_cat);
    cudaGetSymbolAddress((void**)&pPart, g_part);

    cudaFuncSetAttribute(fusedz_kernel, cudaFuncAttributeMaxDynamicSharedMemorySize, FZ_SMEM);
    cudaFuncSetAttribute(o23_kernel,    cudaFuncAttributeMaxDynamicSharedMemorySize, O23_SMEM);

    concat_w<<<(MPROJ * CSd + 255) / 256, 256>>>(Wq, Wk, Wv, Wqp, Wkp, Wvp);
    gemm64<<<dim3(NN / 64, MPROJ / 64, 1), 256>>>(pWcat, s, pP, MPROJ, NN, CSd);
    prep_kernel<<<(Hd * NN + 255) / 256, 256>>>(t_r, t_t, gam);
    fusedz_kernel<<<NN * 2, 256, FZ_SMEM>>>(z, Wb);
    o23_kernel<<<dim3(NN / 4, 2), 256, O23_SMEM>>>();
    o3fix_kernel<<<2, 256>>>(t_r, t_t);
    gemm64<<<dim3(NN / 64, CSd / 64, KSPLIT), 256>>>(Ws, pCat, pPart, CSd, NN, CATd);
    reduce_out<<<(CSd * NN + 255) / 256, 256>>>(bs, out);
}

// round 5
// speedup vs baseline: 1.0918x; 1.0918x over previous
#include <cuda_runtime.h>
#include <math.h>

#define NN   512
#define CSd  384
#define CZd  128
#define Hd   12
#define Cd   16
#define PQd  4
#define PVd  8
#define DE   28
#define CATd 2017
#define MPROJ 1152
#define KSPLIT 8

typedef unsigned long long ull;

// ---------------- packed f32x2 helpers ----------------
__device__ __forceinline__ void ffma2(ull& acc, ull a, ull b) {
    asm("fma.rn.f32x2 %0, %1, %2, %0;" : "+l"(acc) : "l"(a), "l"(b));
}
__device__ __forceinline__ ull pk2(float x, float y) {
    ull r; asm("mov.b64 %0, {%1,%2};" : "=l"(r) : "f"(x), "f"(y)); return r;
}
__device__ __forceinline__ void upk2(ull v, float& x, float& y) {
    asm("mov.b64 {%0,%1}, %2;" : "=f"(x), "=f"(y) : "l"(v));
}

// ---------------- device scratch ----------------
__device__ float g_Wcat[MPROJ * CSd];
__device__ float g_P[MPROJ * NN];
__device__ float g_qe[Hd * DE * NN];
__device__ float g_ke[Hd * DE * NN];
__device__ float g_qn[Hd * NN];
__device__ float g_kn[Hd * NN];
__device__ float g_vr[Hd * Cd * NN];
__device__ float g_vg[3 * Hd * PVd * NN];
__device__ float g_o3g[288 * NN];            // global-frame o3 [rr][i]
__device__ float g_cat[CATd * NN];
__device__ float g_part[KSPLIT * CSd * NN];

// ---------------- weight concat ----------------
__global__ void concat_w(const float* __restrict__ Wq, const float* __restrict__ Wk,
                         const float* __restrict__ Wv, const float* __restrict__ Wqp,
                         const float* __restrict__ Wkp, const float* __restrict__ Wvp) {
    int idx = blockIdx.x * 256 + threadIdx.x;
    if (idx >= MPROJ * CSd) return;
    int row = idx / CSd, c = idx % CSd;
    float v;
    if      (row < 192) v = Wq [(row      ) * CSd + c];
    else if (row < 384) v = Wk [(row - 192) * CSd + c];
    else if (row < 576) v = Wv [(row - 384) * CSd + c];
    else if (row < 720) v = Wqp[(row - 576) * CSd + c];
    else if (row < 864) v = Wkp[(row - 720) * CSd + c];
    else                v = Wvp[(row - 864) * CSd + c];
    g_Wcat[idx] = v;
}

// ---------------- tiled GEMM with split-K, pre-packed B ----------------
__global__ __launch_bounds__(256) void gemm64(const float* __restrict__ A,
                                              const float* __restrict__ B,
                                              float* __restrict__ C,
                                              int M, int Nc, int K) {
    int nb = blockIdx.x, mb = blockIdx.y, zb = blockIdx.z;
    int Kc = (K + gridDim.z - 1) / gridDim.z;
    int k0 = zb * Kc;
    int kend = min(K, k0 + Kc);

    __shared__ float As[16][64];
    __shared__ ull   Bs2[16][64];

    int tid = threadIdx.x;
    int ty = tid >> 4, tx = tid & 15;
    ull acc2[2][4];
#pragma unroll
    for (int u = 0; u < 2; ++u)
#pragma unroll
        for (int v = 0; v < 4; ++v) acc2[u][v] = 0ull;

    for (int kk = k0; kk < kend; kk += 16) {
#pragma unroll
        for (int l = 0; l < 4; ++l) {
            int e = tid + l * 256;
            int m = e >> 4, k = e & 15;
            As[k][m] = (kk + k < kend) ? A[(size_t)(mb * 64 + m) * K + kk + k] : 0.f;
        }
#pragma unroll
        for (int l = 0; l < 4; ++l) {
            int e = tid + l * 256;
            int k = e >> 6, n = e & 63;
            float v = (kk + k < kend) ? B[(size_t)(kk + k) * Nc + nb * 64 + n] : 0.f;
            Bs2[k][n] = pk2(v, v);
        }
        __syncthreads();
#pragma unroll
        for (int k = 0; k < 16; ++k) {
            const ull* a2 = (const ull*)&As[k][ty * 4];
            ull a0 = a2[0], a1 = a2[1];
            ull b0 = Bs2[k][tx * 4], b1 = Bs2[k][tx * 4 + 1];
            ull b2 = Bs2[k][tx * 4 + 2], b3 = Bs2[k][tx * 4 + 3];
            ffma2(acc2[0][0], a0, b0); ffma2(acc2[0][1], a0, b1);
            ffma2(acc2[0][2], a0, b2); ffma2(acc2[0][3], a0, b3);
            ffma2(acc2[1][0], a1, b0); ffma2(acc2[1][1], a1, b1);
            ffma2(acc2[1][2], a1, b2); ffma2(acc2[1][3], a1, b3);
        }
        __syncthreads();
    }
    float* Cz = C + (size_t)zb * M * Nc;
#pragma unroll
    for (int u = 0; u < 2; ++u)
#pragma unroll
        for (int v = 0; v < 4; ++v) {
            float lo, hi;
            upk2(acc2[u][v], lo, hi);
            Cz[(size_t)(mb * 64 + ty * 4 + u * 2    ) * Nc + nb * 64 + tx * 4 + v] = lo;
            Cz[(size_t)(mb * 64 + ty * 4 + u * 2 + 1) * Nc + nb * 64 + tx * 4 + v] = hi;
        }
}

// ---------------- prep: parallel over (h, i) ----------------
__global__ void prep_kernel(const float* __restrict__ t_r, const float* __restrict__ t_t,
                            const float* __restrict__ gamma) {
    int idx = blockIdx.x * 256 + threadIdx.x;
    if (idx >= Hd * NN) return;
    int h = idx / NN, i = idx % NN;
    const float w_c = 0.23570226039551584f;
    float R[9], T[3];
#pragma unroll
    for (int r = 0; r < 9; ++r) R[r] = t_r[i * 9 + r];
#pragma unroll
    for (int c = 0; c < 3; ++c) T[c] = t_t[i * 3 + c];

    float x = gamma[h];
    float sp = (x > 20.f) ? x : log1pf(expf(x));
    float g = sp * w_c * 0.5f;

#pragma unroll
    for (int c = 0; c < Cd; ++c) {
        g_qe[(h * DE + c) * NN + i] = g_P[(      c * Hd + h) * NN + i] * 0.25f;
        g_ke[(h * DE + c) * NN + i] = g_P[(192 + c * Hd + h) * NN + i];
    }
    float qn = 0.f, kn = 0.f;
#pragma unroll
    for (int p = 0; p < PQd; ++p) {
        float q0 = g_P[(576 +  0 + h * 4 + p) * NN + i];
        float q1 = g_P[(576 + 48 + h * 4 + p) * NN + i];
        float q2 = g_P[(576 + 96 + h * 4 + p) * NN + i];
        float k0 = g_P[(720 +  0 + h * 4 + p) * NN + i];
        float k1 = g_P[(720 + 48 + h * 4 + p) * NN + i];
        float k2 = g_P[(720 + 96 + h * 4 + p) * NN + i];
#pragma unroll
        for (int co = 0; co < 3; ++co) {
            float qg = R[co * 3] * q0 + R[co * 3 + 1] * q1 + R[co * 3 + 2] * q2 + T[co];
            float kg = R[co * 3] * k0 + R[co * 3 + 1] * k1 + R[co * 3 + 2] * k2 + T[co];
            g_qe[(h * DE + 16 + co * 4 + p) * NN + i] = 2.f * g * qg;
            g_ke[(h * DE + 16 + co * 4 + p) * NN + i] = kg;
            qn += qg * qg;
            kn += kg * kg;
        }
    }
    g_qn[h * NN + i] = g * qn;
    g_kn[h * NN + i] = g * kn;

#pragma unroll
    for (int c = 0; c < Cd; ++c)
        g_vr[(h * Cd + c) * NN + i] = g_P[(384 + c * Hd + h) * NN + i];

#pragma unroll
    for (int p = 0; p < PVd; ++p) {
        float v0 = g_P[(864 +   0 + h * 8 + p) * NN + i];
        float v1 = g_P[(864 +  96 + h * 8 + p) * NN + i];
        float v2 = g_P[(864 + 192 + h * 8 + p) * NN + i];
#pragma unroll
        for (int co = 0; co < 3; ++co)
            g_vg[(co * 96 + h * 8 + p) * NN + i] =
                R[co * 3] * v0 + R[co * 3 + 1] * v1 + R[co * 3 + 2] * v2 + T[co];
    }
}

// ================= MEGA kernel: warp = head, lane = 16 j's =================
// One block per query row i. 12 warps (one per head). Lane l owns j in
// quads {l, l+32, l+64, l+96} (16 j = 8 packed pairs).
// Phases: bias (z tiles in smem, W broadcast), qk (ke streamed), warp-local
// softmax (probs stay in regs), o1 (z tiles again, L2-hot), o2/o3 (v rows).
// smem: zt[16][512]f @0 (32768) | Wt[128][12]f @32768 (6144)
//       | QE[336]f @38912 (1344) | QN[12]f @40256 (48) -> 40320 B
#define MG_SMEM 40320

__global__ __launch_bounds__(384, 2) void mega_kernel(const float* __restrict__ Z,
                                                      const float* __restrict__ Wb) {
    extern __shared__ char smraw[];
    float* zt  = (float*)smraw;              // [16][512]
    float* Wt  = (float*)(smraw + 32768);    // [c][h]
    float* QE  = (float*)(smraw + 38912);    // [h][d]
    float* QNs = (float*)(smraw + 40256);    // [h]

    const int tid = threadIdx.x;
    const int i = blockIdx.x;
    const int h = tid >> 5, lane = tid & 31;
    const float w_l = 0.5773502691896258f;

    for (int t = tid; t < CZd * Hd; t += 384) Wt[t] = Wb[(t % 12) * CZd + (t / 12)];
    for (int t = tid; t < Hd * DE; t += 384) QE[t] = g_qe[(size_t)t * NN + i];
    if (tid < 12) QNs[tid] = g_qn[tid * NN + i];

    ull acc[8];
#pragma unroll
    for (int t = 0; t < 8; ++t) acc[t] = 0ull;

    // ---------- Phase A: bias = Wb @ z (z staged in 16-c tiles) ----------
    for (int ct = 0; ct < 8; ++ct) {
        __syncthreads();
        for (int e = tid; e < 2048; e += 384) {
            int cc = e >> 7, c4 = e & 127;
            ((float4*)zt)[cc * 128 + c4] =
                ((const float4*)(Z + ((size_t)(ct * 16 + cc) * NN + i) * NN))[c4];
        }
        __syncthreads();
#pragma unroll 4
        for (int cc = 0; cc < 16; ++cc) {
            float w = Wt[(ct * 16 + cc) * 12 + h];
            ull w2 = pk2(w, w);
            const ulonglong2* zrow = (const ulonglong2*)(zt + cc * NN);
#pragma unroll
            for (int t = 0; t < 4; ++t) {
                ulonglong2 zz = zrow[lane + 32 * t];
                ffma2(acc[2 * t],     w2, zz.x);
                ffma2(acc[2 * t + 1], w2, zz.y);
            }
        }
    }

    // ---------- qk + distance (28 augmented dims, ke streamed) ----------
#pragma unroll 4
    for (int d = 0; d < DE; ++d) {
        float qv = QE[h * DE + d];
        ull q2 = pk2(qv, qv);
        const ulonglong2* ker = (const ulonglong2*)(g_ke + (size_t)(h * DE + d) * NN);
#pragma unroll
        for (int t = 0; t < 4; ++t) {
            ulonglong2 kk = ker[lane + 32 * t];
            ffma2(acc[2 * t],     q2, kk.x);
            ffma2(acc[2 * t + 1], q2, kk.y);
        }
    }

    // ---------- logits + warp-local softmax (probs stay in regs) ----------
    float lv[16];
    {
        float qnh = QNs[h];
        const ulonglong2* knr = (const ulonglong2*)(g_kn + h * NN);
#pragma unroll
        for (int t = 0; t < 4; ++t) {
            ulonglong2 kk = knr[lane + 32 * t];
            float k0, k1, k2, k3;
            upk2(kk.x, k0, k1); upk2(kk.y, k2, k3);
            float a0, a1, a2, a3;
            upk2(acc[2 * t], a0, a1); upk2(acc[2 * t + 1], a2, a3);
            lv[4 * t]     = w_l * (a0 - qnh - k0);
            lv[4 * t + 1] = w_l * (a1 - qnh - k1);
            lv[4 * t + 2] = w_l * (a2 - qnh - k2);
            lv[4 * t + 3] = w_l * (a3 - qnh - k3);
        }
    }
    float m = lv[0];
#pragma unroll
    for (int k = 1; k < 16; ++k) m = fmaxf(m, lv[k]);
#pragma unroll
    for (int o = 16; o; o >>= 1) m = fmaxf(m, __shfl_xor_sync(0xffffffffu, m, o));
    float ssum = 0.f;
#pragma unroll
    for (int k = 0; k < 16; ++k) { lv[k] = __expf(lv[k] - m); ssum += lv[k]; }
#pragma unroll
    for (int o = 16; o; o >>= 1) ssum += __shfl_xor_sync(0xffffffffu, ssum, o);
    float inv = 1.f / ssum;
    ull P[8];
#pragma unroll
    for (int t = 0; t < 4; ++t) {
        P[2 * t]     = pk2(lv[4 * t] * inv,     lv[4 * t + 1] * inv);
        P[2 * t + 1] = pk2(lv[4 * t + 2] * inv, lv[4 * t + 3] * inv);
    }

    // ---------- o1: sum_j p[h,j] z[c,i,j]  (z tiles again, L2-hot) ----------
    for (int ct = 0; ct < 8; ++ct) {
        __syncthreads();
        for (int e = tid; e < 2048; e += 384) {
            int cc = e >> 7, c4 = e & 127;
            ((float4*)zt)[cc * 128 + c4] =
                ((const float4*)(Z + ((size_t)(ct * 16 + cc) * NN + i) * NN))[c4];
        }
        __syncthreads();
#pragma unroll 2
        for (int cc = 0; cc < 16; ++cc) {
            const ulonglong2* zrow = (const ulonglong2*)(zt + cc * NN);
            ull s2 = 0ull;
#pragma unroll
            for (int t = 0; t < 4; ++t) {
                ulonglong2 zz = zrow[lane + 32 * t];
                ffma2(s2, P[2 * t],     zz.x);
                ffma2(s2, P[2 * t + 1], zz.y);
            }
            float lo, hi; upk2(s2, lo, hi);
            float s = lo + hi;
#pragma unroll
            for (int o = 16; o; o >>= 1) s += __shfl_xor_sync(0xffffffffu, s, o);
            if (lane == 0) g_cat[(size_t)((ct * 16 + cc) * Hd + h) * NN + i] = s;
        }
    }

    // ---------- o2: sum_j p[h,j] v[h,c,j] ----------
#pragma unroll 2
    for (int cc = 0; cc < Cd; ++cc) {
        const ulonglong2* vr = (const ulonglong2*)(g_vr + (size_t)(h * Cd + cc) * NN);
        ull s2 = 0ull;
#pragma unroll
        for (int t = 0; t < 4; ++t) {
            ulonglong2 vv = vr[lane + 32 * t];
            ffma2(s2, P[2 * t],     vv.x);
            ffma2(s2, P[2 * t + 1], vv.y);
        }
        float lo, hi; upk2(s2, lo, hi);
        float s = lo + hi;
#pragma unroll
        for (int o = 16; o; o >>= 1) s += __shfl_xor_sync(0xffffffffu, s, o);
        if (lane == 0) g_cat[(size_t)(1536 + cc * Hd + h) * NN + i] = s;
    }

    // ---------- o3g: sum_j p[h,j] vg[co,h,p,j] ----------
#pragma unroll 2
    for (int r = 0; r < 24; ++r) {
        int row = (r >> 3) * 96 + h * PVd + (r & 7);
        const ulonglong2* vg = (const ulonglong2*)(g_vg + (size_t)row * NN);
        ull s2 = 0ull;
#pragma unroll
        for (int t = 0; t < 4; ++t) {
            ulonglong2 vv = vg[lane + 32 * t];
            ffma2(s2, P[2 * t],     vv.x);
            ffma2(s2, P[2 * t + 1], vv.y);
        }
        float lo, hi; upk2(s2, lo, hi);
        float s = lo + hi;
#pragma unroll
        for (int o = 16; o; o >>= 1) s += __shfl_xor_sync(0xffffffffu, s, o);
        if (lane == 0) g_o3g[(size_t)row * NN + i] = s;
    }
}

// ---------------- o3 inverse transform + norm (per i) ----------------
__global__ void o3fix_kernel(const float* __restrict__ t_r, const float* __restrict__ t_t) {
    int i = blockIdx.x * 256 + threadIdx.x;
    if (i >= NN) return;
    float R[9], T[3];
#pragma unroll
    for (int r = 0; r < 9; ++r) R[r] = t_r[i * 9 + r];
#pragma unroll
    for (int c = 0; c < 3; ++c) T[c] = t_t[i * 3 + c];

    float nrm = 0.f;
    for (int hp = 0; hp < 96; ++hp) {
        float a0 = g_o3g[(size_t)(0 * 96 + hp) * NN + i] - T[0];
        float a1 = g_o3g[(size_t)(1 * 96 + hp) * NN + i] - T[1];
        float a2 = g_o3g[(size_t)(2 * 96 + hp) * NN + i] - T[2];
#pragma unroll
        for (int co = 0; co < 3; ++co) {
            float v = R[co] * a0 + R[3 + co] * a1 + R[6 + co] * a2;
            g_cat[(size_t)(1728 + co * 96 + hp) * NN + i] = v;
            nrm += v * v;
        }
    }
    g_cat[(size_t)2016 * NN + i] = sqrtf(nrm);
}

// ---------------- final reduce ----------------
__global__ void reduce_out(const float* __restrict__ bs, float* __restrict__ out) {
    int idx = blockIdx.x * 256 + threadIdx.x;
    if (idx >= CSd * NN) return;
    int o = idx >> 9;
    float v = bs[o];
#pragma unroll
    for (int zk = 0; zk < KSPLIT; ++zk) v += g_part[(size_t)zk * CSd * NN + idx];
    out[idx] = v;
}

// ---------------- launcher ----------------
extern "C" void kernel_launch(void* const* d_in, const int* in_sizes, int n_in,
                              void* d_out, int out_size) {
    const float* s    = (const float*)d_in[0];
    const float* z    = (const float*)d_in[1];
    const float* t_r  = (const float*)d_in[2];
    const float* t_t  = (const float*)d_in[3];
    const float* Wq   = (const float*)d_in[4];
    const float* Wk   = (const float*)d_in[5];
    const float* Wv   = (const float*)d_in[6];
    const float* Wqp  = (const float*)d_in[7];
    const float* Wkp  = (const float*)d_in[8];
    const float* Wvp  = (const float*)d_in[9];
    const float* Wb   = (const float*)d_in[10];
    const float* gam  = (const float*)d_in[11];
    const float* Ws   = (const float*)d_in[12];
    const float* bs   = (const float*)d_in[13];
    float* out = (float*)d_out;

    float *pWcat, *pP, *pCat, *pPart;
    cudaGetSymbolAddress((void**)&pWcat, g_Wcat);
    cudaGetSymbolAddress((void**)&pP,    g_P);
    cudaGetSymbolAddress((void**)&pCat,  g_cat);
    cudaGetSymbolAddress((void**)&pPart, g_part);

    cudaFuncSetAttribute(mega_kernel, cudaFuncAttributeMaxDynamicSharedMemorySize, MG_SMEM);

    concat_w<<<(MPROJ * CSd + 255) / 256, 256>>>(Wq, Wk, Wv, Wqp, Wkp, Wvp);
    gemm64<<<dim3(NN / 64, MPROJ / 64, 1), 256>>>(pWcat, s, pP, MPROJ, NN, CSd);
    prep_kernel<<<(Hd * NN + 255) / 256, 256>>>(t_r, t_t, gam);
    mega_kernel<<<NN, 384, MG_SMEM>>>(z, Wb);
    o3fix_kernel<<<2, 256>>>(t_r, t_t);
    gemm64<<<dim3(NN / 64, CSd / 64, KSPLIT), 256>>>(Ws, pCat, pPart, CSd, NN, CATd);
    reduce_out<<<(CSd * NN + 255) / 256, 256>>>(bs, out);
}

// round 6
// speedup vs baseline: 1.1126x; 1.0191x over previous
#include <cuda_runtime.h>
#include <math.h>

#define NN   512
#define CSd  384
#define CZd  128
#define Hd   12
#define Cd   16
#define PQd  4
#define PVd  8
#define DE   28
#define CATd 2017
#define MPROJ 1152
#define KSPLIT 8

typedef unsigned long long ull;

// ---------------- packed f32x2 helpers ----------------
__device__ __forceinline__ void ffma2(ull& acc, ull a, ull b) {
    asm("fma.rn.f32x2 %0, %1, %2, %0;" : "+l"(acc) : "l"(a), "l"(b));
}
__device__ __forceinline__ ull pk2(float x, float y) {
    ull r; asm("mov.b64 %0, {%1,%2};" : "=l"(r) : "f"(x), "f"(y)); return r;
}
__device__ __forceinline__ void upk2(ull v, float& x, float& y) {
    asm("mov.b64 {%0,%1}, %2;" : "=f"(x), "=f"(y) : "l"(v));
}

// ---------------- device scratch ----------------
__device__ float g_Wcat[MPROJ * CSd];
__device__ float g_P[MPROJ * NN];
__device__ float g_qe[Hd * DE * NN];
__device__ float g_ke[Hd * DE * NN];
__device__ float g_qn[Hd * NN];
__device__ float g_kn[Hd * NN];
__device__ float g_vr[Hd * Cd * NN];
__device__ float g_vg[3 * Hd * PVd * NN];
__device__ float g_Lqk[Hd * NN * NN];        // qk+dist dot logit part [h][i][j]
__device__ float g_o3g[288 * NN];
__device__ float g_cat[CATd * NN];
__device__ float g_part[KSPLIT * CSd * NN];

// ---------------- weight concat ----------------
__global__ void concat_w(const float* __restrict__ Wq, const float* __restrict__ Wk,
                         const float* __restrict__ Wv, const float* __restrict__ Wqp,
                         const float* __restrict__ Wkp, const float* __restrict__ Wvp) {
    int idx = blockIdx.x * 256 + threadIdx.x;
    if (idx >= MPROJ * CSd) return;
    int row = idx / CSd, c = idx % CSd;
    float v;
    if      (row < 192) v = Wq [(row      ) * CSd + c];
    else if (row < 384) v = Wk [(row - 192) * CSd + c];
    else if (row < 576) v = Wv [(row - 384) * CSd + c];
    else if (row < 720) v = Wqp[(row - 576) * CSd + c];
    else if (row < 864) v = Wkp[(row - 720) * CSd + c];
    else                v = Wvp[(row - 864) * CSd + c];
    g_Wcat[idx] = v;
}

// ---------------- tiled GEMM with split-K, pre-packed B ----------------
__global__ __launch_bounds__(256) void gemm64(const float* __restrict__ A,
                                              const float* __restrict__ B,
                                              float* __restrict__ C,
                                              int M, int Nc, int K) {
    int nb = blockIdx.x, mb = blockIdx.y, zb = blockIdx.z;
    int Kc = (K + gridDim.z - 1) / gridDim.z;
    int k0 = zb * Kc;
    int kend = min(K, k0 + Kc);

    __shared__ float As[16][64];
    __shared__ ull   Bs2[16][64];

    int tid = threadIdx.x;
    int ty = tid >> 4, tx = tid & 15;
    ull acc2[2][4];
#pragma unroll
    for (int u = 0; u < 2; ++u)
#pragma unroll
        for (int v = 0; v < 4; ++v) acc2[u][v] = 0ull;

    for (int kk = k0; kk < kend; kk += 16) {
#pragma unroll
        for (int l = 0; l < 4; ++l) {
            int e = tid + l * 256;
            int m = e >> 4, k = e & 15;
            As[k][m] = (kk + k < kend) ? A[(size_t)(mb * 64 + m) * K + kk + k] : 0.f;
        }
#pragma unroll
        for (int l = 0; l < 4; ++l) {
            int e = tid + l * 256;
            int k = e >> 6, n = e & 63;
            float v = (kk + k < kend) ? B[(size_t)(kk + k) * Nc + nb * 64 + n] : 0.f;
            Bs2[k][n] = pk2(v, v);
        }
        __syncthreads();
#pragma unroll
        for (int k = 0; k < 16; ++k) {
            const ull* a2 = (const ull*)&As[k][ty * 4];
            ull a0 = a2[0], a1 = a2[1];
            ull b0 = Bs2[k][tx * 4], b1 = Bs2[k][tx * 4 + 1];
            ull b2 = Bs2[k][tx * 4 + 2], b3 = Bs2[k][tx * 4 + 3];
            ffma2(acc2[0][0], a0, b0); ffma2(acc2[0][1], a0, b1);
            ffma2(acc2[0][2], a0, b2); ffma2(acc2[0][3], a0, b3);
            ffma2(acc2[1][0], a1, b0); ffma2(acc2[1][1], a1, b1);
            ffma2(acc2[1][2], a1, b2); ffma2(acc2[1][3], a1, b3);
        }
        __syncthreads();
    }
    float* Cz = C + (size_t)zb * M * Nc;
#pragma unroll
    for (int u = 0; u < 2; ++u)
#pragma unroll
        for (int v = 0; v < 4; ++v) {
            float lo, hi;
            upk2(acc2[u][v], lo, hi);
            Cz[(size_t)(mb * 64 + ty * 4 + u * 2    ) * Nc + nb * 64 + tx * 4 + v] = lo;
            Cz[(size_t)(mb * 64 + ty * 4 + u * 2 + 1) * Nc + nb * 64 + tx * 4 + v] = hi;
        }
}

// ---------------- prep: parallel over (h, i) ----------------
__global__ void prep_kernel(const float* __restrict__ t_r, const float* __restrict__ t_t,
                            const float* __restrict__ gamma) {
    int idx = blockIdx.x * 256 + threadIdx.x;
    if (idx >= Hd * NN) return;
    int h = idx / NN, i = idx % NN;
    const float w_c = 0.23570226039551584f;
    float R[9], T[3];
#pragma unroll
    for (int r = 0; r < 9; ++r) R[r] = t_r[i * 9 + r];
#pragma unroll
    for (int c = 0; c < 3; ++c) T[c] = t_t[i * 3 + c];

    float x = gamma[h];
    float sp = (x > 20.f) ? x : log1pf(expf(x));
    float g = sp * w_c * 0.5f;

#pragma unroll
    for (int c = 0; c < Cd; ++c) {
        g_qe[(h * DE + c) * NN + i] = g_P[(      c * Hd + h) * NN + i] * 0.25f;
        g_ke[(h * DE + c) * NN + i] = g_P[(192 + c * Hd + h) * NN + i];
    }
    float qn = 0.f, kn = 0.f;
#pragma unroll
    for (int p = 0; p < PQd; ++p) {
        float q0 = g_P[(576 +  0 + h * 4 + p) * NN + i];
        float q1 = g_P[(576 + 48 + h * 4 + p) * NN + i];
        float q2 = g_P[(576 + 96 + h * 4 + p) * NN + i];
        float k0 = g_P[(720 +  0 + h * 4 + p) * NN + i];
        float k1 = g_P[(720 + 48 + h * 4 + p) * NN + i];
        float k2 = g_P[(720 + 96 + h * 4 + p) * NN + i];
#pragma unroll
        for (int co = 0; co < 3; ++co) {
            float qg = R[co * 3] * q0 + R[co * 3 + 1] * q1 + R[co * 3 + 2] * q2 + T[co];
            float kg = R[co * 3] * k0 + R[co * 3 + 1] * k1 + R[co * 3 + 2] * k2 + T[co];
            g_qe[(h * DE + 16 + co * 4 + p) * NN + i] = 2.f * g * qg;
            g_ke[(h * DE + 16 + co * 4 + p) * NN + i] = kg;
            qn += qg * qg;
            kn += kg * kg;
        }
    }
    g_qn[h * NN + i] = g * qn;
    g_kn[h * NN + i] = g * kn;

#pragma unroll
    for (int c = 0; c < Cd; ++c)
        g_vr[(h * Cd + c) * NN + i] = g_P[(384 + c * Hd + h) * NN + i];

#pragma unroll
    for (int p = 0; p < PVd; ++p) {
        float v0 = g_P[(864 +   0 + h * 8 + p) * NN + i];
        float v1 = g_P[(864 +  96 + h * 8 + p) * NN + i];
        float v2 = g_P[(864 + 192 + h * 8 + p) * NN + i];
#pragma unroll
        for (int co = 0; co < 3; ++co)
            g_vg[(co * 96 + h * 8 + p) * NN + i] =
                R[co * 3] * v0 + R[co * 3 + 1] * v1 + R[co * 3 + 2] * v2 + T[co];
    }
}

// ---------------- qk batched GEMM: Lqk[h] = qe[h]^T (28xN) . ke[h] (28xN) ----------------
__global__ __launch_bounds__(256) void qk_gemm() {
    __shared__ float As[32][64];
    __shared__ ull   Bs2[32][64];
    const int h = blockIdx.z, mb = blockIdx.y, nb = blockIdx.x;
    const float* Aq = g_qe + (size_t)h * DE * NN;
    const float* Bk = g_ke + (size_t)h * DE * NN;
    int tid = threadIdx.x, ty = tid >> 4, tx = tid & 15;

#pragma unroll
    for (int l = 0; l < 8; ++l) {
        int e = tid + l * 256, k = e >> 6, m = e & 63;
        if (k < DE) {
            As[k][m] = Aq[k * NN + mb * 64 + m];
            float v = Bk[k * NN + nb * 64 + m];
            Bs2[k][m] = pk2(v, v);
        }
    }
    __syncthreads();

    ull acc2[2][4];
#pragma unroll
    for (int u = 0; u < 2; ++u)
#pragma unroll
        for (int v = 0; v < 4; ++v) acc2[u][v] = 0ull;

#pragma unroll
    for (int k = 0; k < DE; ++k) {
        const ull* a2 = (const ull*)&As[k][ty * 4];
        ull a0 = a2[0], a1 = a2[1];
        ull b0 = Bs2[k][tx * 4], b1 = Bs2[k][tx * 4 + 1];
        ull b2 = Bs2[k][tx * 4 + 2], b3 = Bs2[k][tx * 4 + 3];
        ffma2(acc2[0][0], a0, b0); ffma2(acc2[0][1], a0, b1);
        ffma2(acc2[0][2], a0, b2); ffma2(acc2[0][3], a0, b3);
        ffma2(acc2[1][0], a1, b0); ffma2(acc2[1][1], a1, b1);
        ffma2(acc2[1][2], a1, b2); ffma2(acc2[1][3], a1, b3);
    }
    float* C = g_Lqk + (size_t)h * NN * NN;
#pragma unroll
    for (int u = 0; u < 2; ++u)
#pragma unroll
        for (int v = 0; v < 4; ++v) {
            float lo, hi;
            upk2(acc2[u][v], lo, hi);
            C[(size_t)(mb * 64 + ty * 4 + u * 2    ) * NN + nb * 64 + tx * 4 + v] = lo;
            C[(size_t)(mb * 64 + ty * 4 + u * 2 + 1) * NN + nb * 64 + tx * 4 + v] = hi;
        }
}

// ================= mega2: thread = j-quad, 12 heads in registers =================
// block = 256 thr = 2 query rows x 128 threads (thread t owns j in [4t, 4t+4))
// smem: W2s[128*12] ull @0 (12288) | Ps[2][12][256] ull @12288 (49152)
//       | red[2][12][4] f @61440 (384) | qns[2][12] f @61824 (96)
#define MG2_SMEM 61952

__global__ __launch_bounds__(256, 2) void mega2(const float* __restrict__ Z,
                                                const float* __restrict__ Wb) {
    extern __shared__ char smraw[];
    ull*   W2s = (ull*)smraw;
    ull*   Ps  = (ull*)(smraw + 12288);
    float* red = (float*)(smraw + 61440);
    float* qns = (float*)(smraw + 61824);

    const int tid = threadIdx.x;
    const int u = tid >> 7, t = tid & 127;
    const int i = blockIdx.x * 2 + u;
    const int lane = tid & 31, wu = t >> 5;
    const float w_l = 0.5773502691896258f;

    for (int e = tid; e < CZd * Hd; e += 256) {
        int c = e / 12, h = e % 12;
        float w = Wb[h * CZd + c];
        W2s[e] = pk2(w, w);
    }
    if (tid < 24) qns[tid] = g_qn[(tid % 12) * NN + blockIdx.x * 2 + tid / 12];
    __syncthreads();

    // ---------- Phase A: bias = Wb @ z ----------
    ull acc[Hd][2];
#pragma unroll
    for (int h = 0; h < Hd; ++h) { acc[h][0] = 0ull; acc[h][1] = 0ull; }

    const float4* z4 = (const float4*)Z;
#pragma unroll 4
    for (int c = 0; c < CZd; ++c) {
        float4 zv = __ldg(&z4[((size_t)c * NN + i) * 128 + t]);
        ull zx = pk2(zv.x, zv.y), zy = pk2(zv.z, zv.w);
#pragma unroll
        for (int h = 0; h < Hd; ++h) {
            ull w2 = W2s[c * 12 + h];
            ffma2(acc[h][0], w2, zx);
            ffma2(acc[h][1], w2, zy);
        }
    }

    // ---------- logits = w_l*(bias + Lqk - qn - kn) ----------
    float lv[Hd][4];
#pragma unroll
    for (int h = 0; h < Hd; ++h) {
        float4 qk = __ldg((const float4*)(g_Lqk + ((size_t)h * NN + i) * NN) + t);
        float4 kn = __ldg((const float4*)(g_kn + h * NN) + t);
        float qn = qns[u * 12 + h];
        float a0, a1, a2, a3;
        upk2(acc[h][0], a0, a1);
        upk2(acc[h][1], a2, a3);
        lv[h][0] = w_l * (a0 + qk.x - qn - kn.x);
        lv[h][1] = w_l * (a1 + qk.y - qn - kn.y);
        lv[h][2] = w_l * (a2 + qk.z - qn - kn.z);
        lv[h][3] = w_l * (a3 + qk.w - qn - kn.w);
    }

    // ---------- softmax over 128 threads x 4 j per (i,h) ----------
    float mx[Hd];
#pragma unroll
    for (int h = 0; h < Hd; ++h) {
        float m = fmaxf(fmaxf(lv[h][0], lv[h][1]), fmaxf(lv[h][2], lv[h][3]));
#pragma unroll
        for (int o = 16; o; o >>= 1) m = fmaxf(m, __shfl_xor_sync(0xffffffffu, m, o));
        if (lane == 0) red[(u * 12 + h) * 4 + wu] = m;
    }
    __syncthreads();
#pragma unroll
    for (int h = 0; h < Hd; ++h) {
        const float* r = &red[(u * 12 + h) * 4];
        mx[h] = fmaxf(fmaxf(r[0], r[1]), fmaxf(r[2], r[3]));
    }
    float ws[Hd];
#pragma unroll
    for (int h = 0; h < Hd; ++h) {
        float s = 0.f;
#pragma unroll
        for (int k = 0; k < 4; ++k) { lv[h][k] = __expf(lv[h][k] - mx[h]); s += lv[h][k]; }
#pragma unroll
        for (int o = 16; o; o >>= 1) s += __shfl_xor_sync(0xffffffffu, s, o);
        ws[h] = s;
    }
    __syncthreads();
#pragma unroll
    for (int h = 0; h < Hd; ++h)
        if (lane == 0) red[(u * 12 + h) * 4 + wu] = ws[h];
    __syncthreads();
#pragma unroll
    for (int h = 0; h < Hd; ++h) {
        const float* r = &red[(u * 12 + h) * 4];
        float inv = 1.f / (r[0] + r[1] + r[2] + r[3]);
        Ps[(u * 12 + h) * 256 + 2 * t]     = pk2(lv[h][0] * inv, lv[h][1] * inv);
        Ps[(u * 12 + h) * 256 + 2 * t + 1] = pk2(lv[h][2] * inv, lv[h][3] * inv);
    }
    __syncthreads();

    // ---------- Phase B: o1[c,h] = sum_j P[h,j] z[c,i,j] (thread = c) ----------
    {
        const int c = t;
        ull a1[Hd];
#pragma unroll
        for (int h = 0; h < Hd; ++h) a1[h] = 0ull;
        const ulonglong2* zc = (const ulonglong2*)(Z + ((size_t)c * NN + i) * NN);
        const ulonglong2* Pp = (const ulonglong2*)(Ps + (size_t)u * 12 * 256);
#pragma unroll 2
        for (int q = 0; q < 128; ++q) {
            ulonglong2 zz = __ldg(&zc[q]);
#pragma unroll
            for (int h = 0; h < Hd; ++h) {
                ulonglong2 pp = Pp[h * 128 + q];
                ffma2(a1[h], pp.x, zz.x);
                ffma2(a1[h], pp.y, zz.y);
            }
        }
#pragma unroll
        for (int h = 0; h < Hd; ++h) {
            float lo, hi;
            upk2(a1[h], lo, hi);
            g_cat[(size_t)(c * Hd + h) * NN + i] = lo + hi;
        }
    }

    // ---------- Phase C: o2 + o3g (thread = output row) ----------
    for (int r = t; r < 480; r += 128) {
        const ulonglong2* vrow;
        int h;
        if (r < 192) { vrow = (const ulonglong2*)(g_vr + (size_t)r * NN); h = r >> 4; }
        else { int rr = r - 192; vrow = (const ulonglong2*)(g_vg + (size_t)rr * NN); h = (rr % 96) >> 3; }
        const ulonglong2* Ph = (const ulonglong2*)(Ps + ((size_t)u * 12 + h) * 256);
        ull s2 = 0ull;
#pragma unroll 2
        for (int q = 0; q < 128; ++q) {
            ulonglong2 vv = __ldg(&vrow[q]);
            ulonglong2 pp = Ph[q];
            ffma2(s2, pp.x, vv.x);
            ffma2(s2, pp.y, vv.y);
        }
        float lo, hi;
        upk2(s2, lo, hi);
        float s = lo + hi;
        if (r < 192) g_cat[(size_t)(1536 + (r & 15) * Hd + h) * NN + i] = s;
        else         g_o3g[(size_t)(r - 192) * NN + i] = s;
    }
}

// ---------------- o3 inverse transform + norm (warp per i) ----------------
__global__ void o3fix2(const float* __restrict__ t_r, const float* __restrict__ t_t) {
    int warp = threadIdx.x >> 5, lane = threadIdx.x & 31;
    int i = blockIdx.x * 8 + warp;
    float R[9], T[3];
#pragma unroll
    for (int r = 0; r < 9; ++r) R[r] = t_r[i * 9 + r];
#pragma unroll
    for (int c = 0; c < 3; ++c) T[c] = t_t[i * 3 + c];

    float nrm = 0.f;
    for (int hp = lane; hp < 96; hp += 32) {
        float a0 = g_o3g[(size_t)(0 * 96 + hp) * NN + i] - T[0];
        float a1 = g_o3g[(size_t)(1 * 96 + hp) * NN + i] - T[1];
        float a2 = g_o3g[(size_t)(2 * 96 + hp) * NN + i] - T[2];
#pragma unroll
        for (int co = 0; co < 3; ++co) {
            float v = R[co] * a0 + R[3 + co] * a1 + R[6 + co] * a2;
            g_cat[(size_t)(1728 + co * 96 + hp) * NN + i] = v;
            nrm += v * v;
        }
    }
#pragma unroll
    for (int o = 16; o; o >>= 1) nrm += __shfl_xor_sync(0xffffffffu, nrm, o);
    if (lane == 0) g_cat[(size_t)2016 * NN + i] = sqrtf(nrm);
}

// ---------------- final reduce ----------------
__global__ void reduce_out(const float* __restrict__ bs, float* __restrict__ out) {
    int idx = blockIdx.x * 256 + threadIdx.x;
    if (idx >= CSd * NN) return;
    int o = idx >> 9;
    float v = bs[o];
#pragma unroll
    for (int zk = 0; zk < KSPLIT; ++zk) v += g_part[(size_t)zk * CSd * NN + idx];
    out[idx] = v;
}

// ---------------- launcher ----------------
extern "C" void kernel_launch(void* const* d_in, const int* in_sizes, int n_in,
                              void* d_out, int out_size) {
    const float* s    = (const float*)d_in[0];
    const float* z    = (const float*)d_in[1];
    const float* t_r  = (const float*)d_in[2];
    const float* t_t  = (const float*)d_in[3];
    const float* Wq   = (const float*)d_in[4];
    const float* Wk   = (const float*)d_in[5];
    const float* Wv   = (const float*)d_in[6];
    const float* Wqp  = (const float*)d_in[7];
    const float* Wkp  = (const float*)d_in[8];
    const float* Wvp  = (const float*)d_in[9];
    const float* Wb   = (const float*)d_in[10];
    const float* gam  = (const float*)d_in[11];
    const float* Ws   = (const float*)d_in[12];
    const float* bs   = (const float*)d_in[13];
    float* out = (float*)d_out;

    float *pWcat, *pP, *pCat, *pPart;
    cudaGetSymbolAddress((void**)&pWcat, g_Wcat);
    cudaGetSymbolAddress((void**)&pP,    g_P);
    cudaGetSymbolAddress((void**)&pCat,  g_cat);
    cudaGetSymbolAddress((void**)&pPart, g_part);

    cudaFuncSetAttribute(mega2, cudaFuncAttributeMaxDynamicSharedMemorySize, MG2_SMEM);

    concat_w<<<(MPROJ * CSd + 255) / 256, 256>>>(Wq, Wk, Wv, Wqp, Wkp, Wvp);
    gemm64<<<dim3(NN / 64, MPROJ / 64, 1), 256>>>(pWcat, s, pP, MPROJ, NN, CSd);
    prep_kernel<<<(Hd * NN + 255) / 256, 256>>>(t_r, t_t, gam);
    qk_gemm<<<dim3(NN / 64, NN / 64, Hd), 256>>>();
    mega2<<<NN / 2, 256, MG2_SMEM>>>(z, Wb);
    o3fix2<<<NN / 8, 256>>>(t_r, t_t);
    gemm64<<<dim3(NN / 64, CSd / 64, KSPLIT), 256>>>(Ws, pCat, pPart, CSd, NN, CATd);
    reduce_out<<<(CSd * NN + 255) / 256, 256>>>(bs, out);
}

// round 7
// speedup vs baseline: 1.2543x; 1.1274x over previous
#include <cuda_runtime.h>
#include <math.h>

#define NN   512
#define CSd  384
#define CZd  128
#define Hd   12
#define Cd   16
#define PQd  4
#define PVd  8
#define DE   28
#define CATd 2017
#define MPROJ 1152
#define KSPLIT 8

typedef unsigned long long ull;

// ---------------- packed f32x2 helpers ----------------
__device__ __forceinline__ void ffma2(ull& acc, ull a, ull b) {
    asm("fma.rn.f32x2 %0, %1, %2, %0;" : "+l"(acc) : "l"(a), "l"(b));
}
__device__ __forceinline__ ull pk2(float x, float y) {
    ull r; asm("mov.b64 %0, {%1,%2};" : "=l"(r) : "f"(x), "f"(y)); return r;
}
__device__ __forceinline__ void upk2(ull v, float& x, float& y) {
    asm("mov.b64 {%0,%1}, %2;" : "=f"(x), "=f"(y) : "l"(v));
}

// ---------------- device scratch ----------------
__device__ float g_Wcat[MPROJ * CSd];
__device__ float g_P[MPROJ * NN];
__device__ float g_qe[Hd * DE * NN];
__device__ float g_ke[Hd * DE * NN];
__device__ float g_qn[Hd * NN];
__device__ float g_kn[Hd * NN];
__device__ float g_vr[Hd * Cd * NN];
__device__ float g_vg[3 * Hd * PVd * NN];
__device__ float g_Lqk[Hd * NN * NN];        // qk - dist partial [h][i][j]
__device__ float g_bias[2 * Hd * NN * NN];   // bias partials [ks][h][i][j]
__device__ float g_A[NN * Hd * NN];          // probs [i][h][j]
__device__ float g_o3g[288 * NN];
__device__ float g_cat[CATd * NN];
__device__ float g_part[KSPLIT * CSd * NN];

// ---------------- weight concat ----------------
__global__ void concat_w(const float* __restrict__ Wq, const float* __restrict__ Wk,
                         const float* __restrict__ Wv, const float* __restrict__ Wqp,
                         const float* __restrict__ Wkp, const float* __restrict__ Wvp) {
    int idx = blockIdx.x * 256 + threadIdx.x;
    if (idx >= MPROJ * CSd) return;
    int row = idx / CSd, c = idx % CSd;
    float v;
    if      (row < 192) v = Wq [(row      ) * CSd + c];
    else if (row < 384) v = Wk [(row - 192) * CSd + c];
    else if (row < 576) v = Wv [(row - 384) * CSd + c];
    else if (row < 720) v = Wqp[(row - 576) * CSd + c];
    else if (row < 864) v = Wkp[(row - 720) * CSd + c];
    else                v = Wvp[(row - 864) * CSd + c];
    g_Wcat[idx] = v;
}

// ---------------- tiled GEMM with split-K, pre-packed B ----------------
__global__ __launch_bounds__(256) void gemm64(const float* __restrict__ A,
                                              const float* __restrict__ B,
                                              float* __restrict__ C,
                                              int M, int Nc, int K) {
    int nb = blockIdx.x, mb = blockIdx.y, zb = blockIdx.z;
    int Kc = (K + gridDim.z - 1) / gridDim.z;
    int k0 = zb * Kc;
    int kend = min(K, k0 + Kc);

    __shared__ float As[16][64];
    __shared__ ull   Bs2[16][64];

    int tid = threadIdx.x;
    int ty = tid >> 4, tx = tid & 15;
    ull acc2[2][4];
#pragma unroll
    for (int u = 0; u < 2; ++u)
#pragma unroll
        for (int v = 0; v < 4; ++v) acc2[u][v] = 0ull;

    for (int kk = k0; kk < kend; kk += 16) {
#pragma unroll
        for (int l = 0; l < 4; ++l) {
            int e = tid + l * 256;
            int m = e >> 4, k = e & 15;
            As[k][m] = (kk + k < kend) ? A[(size_t)(mb * 64 + m) * K + kk + k] : 0.f;
        }
#pragma unroll
        for (int l = 0; l < 4; ++l) {
            int e = tid + l * 256;
            int k = e >> 6, n = e & 63;
            float v = (kk + k < kend) ? B[(size_t)(kk + k) * Nc + nb * 64 + n] : 0.f;
            Bs2[k][n] = pk2(v, v);
        }
        __syncthreads();
#pragma unroll
        for (int k = 0; k < 16; ++k) {
            const ull* a2 = (const ull*)&As[k][ty * 4];
            ull a0 = a2[0], a1 = a2[1];
            ull b0 = Bs2[k][tx * 4], b1 = Bs2[k][tx * 4 + 1];
            ull b2 = Bs2[k][tx * 4 + 2], b3 = Bs2[k][tx * 4 + 3];
            ffma2(acc2[0][0], a0, b0); ffma2(acc2[0][1], a0, b1);
            ffma2(acc2[0][2], a0, b2); ffma2(acc2[0][3], a0, b3);
            ffma2(acc2[1][0], a1, b0); ffma2(acc2[1][1], a1, b1);
            ffma2(acc2[1][2], a1, b2); ffma2(acc2[1][3], a1, b3);
        }
        __syncthreads();
    }
    float* Cz = C + (size_t)zb * M * Nc;
#pragma unroll
    for (int u = 0; u < 2; ++u)
#pragma unroll
        for (int v = 0; v < 4; ++v) {
            float lo, hi;
            upk2(acc2[u][v], lo, hi);
            Cz[(size_t)(mb * 64 + ty * 4 + u * 2    ) * Nc + nb * 64 + tx * 4 + v] = lo;
            Cz[(size_t)(mb * 64 + ty * 4 + u * 2 + 1) * Nc + nb * 64 + tx * 4 + v] = hi;
        }
}

// ---------------- prep: parallel over (h, i) ----------------
__global__ void prep_kernel(const float* __restrict__ t_r, const float* __restrict__ t_t,
                            const float* __restrict__ gamma) {
    int idx = blockIdx.x * 256 + threadIdx.x;
    if (idx >= Hd * NN) return;
    int h = idx / NN, i = idx % NN;
    const float w_c = 0.23570226039551584f;
    float R[9], T[3];
#pragma unroll
    for (int r = 0; r < 9; ++r) R[r] = t_r[i * 9 + r];
#pragma unroll
    for (int c = 0; c < 3; ++c) T[c] = t_t[i * 3 + c];

    float x = gamma[h];
    float sp = (x > 20.f) ? x : log1pf(expf(x));
    float g = sp * w_c * 0.5f;

#pragma unroll
    for (int c = 0; c < Cd; ++c) {
        g_qe[(h * DE + c) * NN + i] = g_P[(      c * Hd + h) * NN + i] * 0.25f;
        g_ke[(h * DE + c) * NN + i] = g_P[(192 + c * Hd + h) * NN + i];
    }
    float qn = 0.f, kn = 0.f;
#pragma unroll
    for (int p = 0; p < PQd; ++p) {
        float q0 = g_P[(576 +  0 + h * 4 + p) * NN + i];
        float q1 = g_P[(576 + 48 + h * 4 + p) * NN + i];
        float q2 = g_P[(576 + 96 + h * 4 + p) * NN + i];
        float k0 = g_P[(720 +  0 + h * 4 + p) * NN + i];
        float k1 = g_P[(720 + 48 + h * 4 + p) * NN + i];
        float k2 = g_P[(720 + 96 + h * 4 + p) * NN + i];
#pragma unroll
        for (int co = 0; co < 3; ++co) {
            float qg = R[co * 3] * q0 + R[co * 3 + 1] * q1 + R[co * 3 + 2] * q2 + T[co];
            float kg = R[co * 3] * k0 + R[co * 3 + 1] * k1 + R[co * 3 + 2] * k2 + T[co];
            g_qe[(h * DE + 16 + co * 4 + p) * NN + i] = 2.f * g * qg;
            g_ke[(h * DE + 16 + co * 4 + p) * NN + i] = kg;
            qn += qg * qg;
            kn += kg * kg;
        }
    }
    g_qn[h * NN + i] = g * qn;
    g_kn[h * NN + i] = g * kn;

#pragma unroll
    for (int c = 0; c < Cd; ++c)
        g_vr[(h * Cd + c) * NN + i] = g_P[(384 + c * Hd + h) * NN + i];

#pragma unroll
    for (int p = 0; p < PVd; ++p) {
        float v0 = g_P[(864 +   0 + h * 8 + p) * NN + i];
        float v1 = g_P[(864 +  96 + h * 8 + p) * NN + i];
        float v2 = g_P[(864 + 192 + h * 8 + p) * NN + i];
#pragma unroll
        for (int co = 0; co < 3; ++co)
            g_vg[(co * 96 + h * 8 + p) * NN + i] =
                R[co * 3] * v0 + R[co * 3 + 1] * v1 + R[co * 3 + 2] * v2 + T[co];
    }
}

// ---------------- qk batched GEMM: Lqk[h] = qe[h]^T . ke[h] ----------------
__global__ __launch_bounds__(256) void qk_gemm() {
    __shared__ float As[32][64];
    __shared__ ull   Bs2[32][64];
    const int h = blockIdx.z, mb = blockIdx.y, nb = blockIdx.x;
    const float* Aq = g_qe + (size_t)h * DE * NN;
    const float* Bk = g_ke + (size_t)h * DE * NN;
    int tid = threadIdx.x, ty = tid >> 4, tx = tid & 15;

#pragma unroll
    for (int l = 0; l < 8; ++l) {
        int e = tid + l * 256, k = e >> 6, m = e & 63;
        if (k < DE) {
            As[k][m] = Aq[k * NN + mb * 64 + m];
            float v = Bk[k * NN + nb * 64 + m];
            Bs2[k][m] = pk2(v, v);
        }
    }
    __syncthreads();

    ull acc2[2][4];
#pragma unroll
    for (int u = 0; u < 2; ++u)
#pragma unroll
        for (int v = 0; v < 4; ++v) acc2[u][v] = 0ull;

#pragma unroll
    for (int k = 0; k < DE; ++k) {
        const ull* a2 = (const ull*)&As[k][ty * 4];
        ull a0 = a2[0], a1 = a2[1];
        ull b0 = Bs2[k][tx * 4], b1 = Bs2[k][tx * 4 + 1];
        ull b2 = Bs2[k][tx * 4 + 2], b3 = Bs2[k][tx * 4 + 3];
        ffma2(acc2[0][0], a0, b0); ffma2(acc2[0][1], a0, b1);
        ffma2(acc2[0][2], a0, b2); ffma2(acc2[0][3], a0, b3);
        ffma2(acc2[1][0], a1, b0); ffma2(acc2[1][1], a1, b1);
        ffma2(acc2[1][2], a1, b2); ffma2(acc2[1][3], a1, b3);
    }
    float* C = g_Lqk + (size_t)h * NN * NN;
#pragma unroll
    for (int u = 0; u < 2; ++u)
#pragma unroll
        for (int v = 0; v < 4; ++v) {
            float lo, hi;
            upk2(acc2[u][v], lo, hi);
            C[(size_t)(mb * 64 + ty * 4 + u * 2    ) * NN + nb * 64 + tx * 4 + v] = lo;
            C[(size_t)(mb * 64 + ty * 4 + u * 2 + 1) * NN + nb * 64 + tx * 4 + v] = hi;
        }
}

// ---------------- bias GEMM: [12h x 64c] @ z[c][n], n = (i,j) flattened ----------------
// grid (256, 2): blockIdx.x = n4-block (256 float4 per block), blockIdx.y = c-half
__global__ __launch_bounds__(256) void bias_kernel(const float* __restrict__ Z,
                                                   const float* __restrict__ Wb) {
    __shared__ ull W2s[64 * Hd];
    const int tid = threadIdx.x;
    const int ks = blockIdx.y;
    const int c0 = ks * 64;
    const size_t n4 = (size_t)blockIdx.x * 256 + tid;   // float4 index, 65536 total

    for (int e = tid; e < 64 * Hd; e += 256) {
        int c = e / 12, h = e % 12;
        float w = Wb[h * CZd + c0 + c];
        W2s[e] = pk2(w, w);
    }
    __syncthreads();

    ull acc[Hd][2];
#pragma unroll
    for (int h = 0; h < Hd; ++h) { acc[h][0] = 0ull; acc[h][1] = 0ull; }

    const float4* z4 = (const float4*)Z;
#pragma unroll 4
    for (int c = 0; c < 64; ++c) {
        float4 zv = __ldg(&z4[(size_t)(c0 + c) * 65536 + n4]);
        ull zx = pk2(zv.x, zv.y), zy = pk2(zv.z, zv.w);
#pragma unroll
        for (int h = 0; h < Hd; ++h) {
            ull w2 = W2s[c * 12 + h];
            ffma2(acc[h][0], w2, zx);
            ffma2(acc[h][1], w2, zy);
        }
    }

    float4* out4 = (float4*)g_bias;
#pragma unroll
    for (int h = 0; h < Hd; ++h) {
        float4 o;
        upk2(acc[h][0], o.x, o.y);
        upk2(acc[h][1], o.z, o.w);
        out4[(size_t)(ks * Hd + h) * 65536 + n4] = o;
    }
}

// ---------------- logits + softmax -> probs g_A ----------------
__global__ __launch_bounds__(256) void logits2() {
    __shared__ float red[Hd][8];
    __shared__ float qns[Hd];
    const int i = blockIdx.x;
    const int tid = threadIdx.x;
    const int warp = tid >> 5, lane = tid & 31;
    const float w_l = 0.5773502691896258f;

    if (tid < 12) qns[tid] = g_qn[tid * NN + i];
    __syncthreads();

    float2 lv[Hd];
    size_t base = (size_t)i * NN + 2 * tid;
#pragma unroll
    for (int h = 0; h < Hd; ++h) {
        float2 b0 = *(const float2*)(g_bias + (size_t)h * NN * NN + base);
        float2 b1 = *(const float2*)(g_bias + (size_t)(Hd + h) * NN * NN + base);
        float2 qk = *(const float2*)(g_Lqk + (size_t)h * NN * NN + base);
        float2 kn = *(const float2*)(g_kn + h * NN + 2 * tid);
        float qn = qns[h];
        lv[h].x = w_l * (b0.x + b1.x + qk.x - qn - kn.x);
        lv[h].y = w_l * (b0.y + b1.y + qk.y - qn - kn.y);
    }

    // max
#pragma unroll
    for (int h = 0; h < Hd; ++h) {
        float m = fmaxf(lv[h].x, lv[h].y);
#pragma unroll
        for (int o = 16; o; o >>= 1) m = fmaxf(m, __shfl_xor_sync(0xffffffffu, m, o));
        if (lane == 0) red[h][warp] = m;
    }
    __syncthreads();
    float mx[Hd];
#pragma unroll
    for (int h = 0; h < Hd; ++h) {
        float m = red[h][0];
#pragma unroll
        for (int w = 1; w < 8; ++w) m = fmaxf(m, red[h][w]);
        mx[h] = m;
    }
    __syncthreads();
    // exp + sum
#pragma unroll
    for (int h = 0; h < Hd; ++h) {
        lv[h].x = __expf(lv[h].x - mx[h]);
        lv[h].y = __expf(lv[h].y - mx[h]);
        float s = lv[h].x + lv[h].y;
#pragma unroll
        for (int o = 16; o; o >>= 1) s += __shfl_xor_sync(0xffffffffu, s, o);
        if (lane == 0) red[h][warp] = s;
    }
    __syncthreads();
    float* out = g_A + (size_t)i * Hd * NN;
#pragma unroll
    for (int h = 0; h < Hd; ++h) {
        float s = red[h][0];
#pragma unroll
        for (int w = 1; w < 8; ++w) s += red[h][w];
        float inv = 1.f / s;
        float2 p;
        p.x = lv[h].x * inv;
        p.y = lv[h].y * inv;
        *(float2*)(out + h * NN + 2 * tid) = p;
    }
}

// ---------------- o1: per (i, c-half), warp-per-c ----------------
__global__ __launch_bounds__(256) void o1k(const float* __restrict__ Z) {
    __shared__ ull Ps[Hd * 256];   // probs packed pairs, 24KB
    const int i = blockIdx.x;
    const int ks = blockIdx.y;
    const int tid = threadIdx.x;
    const int warp = tid >> 5, lane = tid & 31;

    {
        const ull* src = (const ull*)(g_A + (size_t)i * Hd * NN);
        for (int e = tid; e < Hd * 256; e += 256) Ps[e] = src[e];
    }
    __syncthreads();
    const ulonglong2* Ps2 = (const ulonglong2*)Ps;

    for (int c = ks * 64 + warp; c < ks * 64 + 64; c += 8) {
        const ulonglong2* zc = (const ulonglong2*)(Z + ((size_t)c * NN + i) * NN);
        ull acc[Hd];
#pragma unroll
        for (int h = 0; h < Hd; ++h) acc[h] = 0ull;
#pragma unroll
        for (int q = 0; q < 4; ++q) {
            ulonglong2 zz = __ldg(&zc[lane + 32 * q]);
#pragma unroll
            for (int h = 0; h < Hd; ++h) {
                ulonglong2 pp = Ps2[h * 128 + lane + 32 * q];
                ffma2(acc[h], pp.x, zz.x);
                ffma2(acc[h], pp.y, zz.y);
            }
        }
#pragma unroll
        for (int h = 0; h < Hd; ++h) {
            float lo, hi;
            upk2(acc[h], lo, hi);
            float s = lo + hi;
#pragma unroll
            for (int o = 16; o; o >>= 1) s += __shfl_xor_sync(0xffffffffu, s, o);
            if (lane == 0) g_cat[(size_t)(c * Hd + h) * NN + i] = s;
        }
    }
}

// ---------------- o2 + o3g: warp-per-row ----------------
__global__ __launch_bounds__(256) void o23k() {
    __shared__ ull Ps[Hd * 256];
    const int i = blockIdx.x;
    const int tid = threadIdx.x;
    const int warp = tid >> 5, lane = tid & 31;

    {
        const ull* src = (const ull*)(g_A + (size_t)i * Hd * NN);
        for (int e = tid; e < Hd * 256; e += 256) Ps[e] = src[e];
    }
    __syncthreads();
    const ulonglong2* Ps2 = (const ulonglong2*)Ps;

    for (int r = warp; r < 480; r += 8) {
        const ulonglong2* vrow;
        int h;
        if (r < 192) { vrow = (const ulonglong2*)(g_vr + (size_t)r * NN); h = r >> 4; }
        else { int rr = r - 192; vrow = (const ulonglong2*)(g_vg + (size_t)rr * NN); h = (rr % 96) >> 3; }
        ull s2 = 0ull;
#pragma unroll
        for (int q = 0; q < 4; ++q) {
            ulonglong2 vv = __ldg(&vrow[lane + 32 * q]);
            ulonglong2 pp = Ps2[h * 128 + lane + 32 * q];
            ffma2(s2, pp.x, vv.x);
            ffma2(s2, pp.y, vv.y);
        }
        float lo, hi;
        upk2(s2, lo, hi);
        float s = lo + hi;
#pragma unroll
        for (int o = 16; o; o >>= 1) s += __shfl_xor_sync(0xffffffffu, s, o);
        if (lane == 0) {
            if (r < 192) g_cat[(size_t)(1536 + (r & 15) * Hd + h) * NN + i] = s;
            else         g_o3g[(size_t)(r - 192) * NN + i] = s;
        }
    }
}

// ---------------- o3 inverse transform + norm (warp per i) ----------------
__global__ void o3fix2(const float* __restrict__ t_r, const float* __restrict__ t_t) {
    int warp = threadIdx.x >> 5, lane = threadIdx.x & 31;
    int i = blockIdx.x * 8 + warp;
    float R[9], T[3];
#pragma unroll
    for (int r = 0; r < 9; ++r) R[r] = t_r[i * 9 + r];
#pragma unroll
    for (int c = 0; c < 3; ++c) T[c] = t_t[i * 3 + c];

    float nrm = 0.f;
    for (int hp = lane; hp < 96; hp += 32) {
        float a0 = g_o3g[(size_t)(0 * 96 + hp) * NN + i] - T[0];
        float a1 = g_o3g[(size_t)(1 * 96 + hp) * NN + i] - T[1];
        float a2 = g_o3g[(size_t)(2 * 96 + hp) * NN + i] - T[2];
#pragma unroll
        for (int co = 0; co < 3; ++co) {
            float v = R[co] * a0 + R[3 + co] * a1 + R[6 + co] * a2;
            g_cat[(size_t)(1728 + co * 96 + hp) * NN + i] = v;
            nrm += v * v;
        }
    }
#pragma unroll
    for (int o = 16; o; o >>= 1) nrm += __shfl_xor_sync(0xffffffffu, nrm, o);
    if (lane == 0) g_cat[(size_t)2016 * NN + i] = sqrtf(nrm);
}

// ---------------- final reduce ----------------
__global__ void reduce_out(const float* __restrict__ bs, float* __restrict__ out) {
    int idx = blockIdx.x * 256 + threadIdx.x;
    if (idx >= CSd * NN) return;
    int o = idx >> 9;
    float v = bs[o];
#pragma unroll
    for (int zk = 0; zk < KSPLIT; ++zk) v += g_part[(size_t)zk * CSd * NN + idx];
    out[idx] = v;
}

// ---------------- launcher ----------------
extern "C" void kernel_launch(void* const* d_in, const int* in_sizes, int n_in,
                              void* d_out, int out_size) {
    const float* s    = (const float*)d_in[0];
    const float* z    = (const float*)d_in[1];
    const float* t_r  = (const float*)d_in[2];
    const float* t_t  = (const float*)d_in[3];
    const float* Wq   = (const float*)d_in[4];
    const float* Wk   = (const float*)d_in[5];
    const float* Wv   = (const float*)d_in[6];
    const float* Wqp  = (const float*)d_in[7];
    const float* Wkp  = (const float*)d_in[8];
    const float* Wvp  = (const float*)d_in[9];
    const float* Wb   = (const float*)d_in[10];
    const float* gam  = (const float*)d_in[11];
    const float* Ws   = (const float*)d_in[12];
    const float* bs   = (const float*)d_in[13];
    float* out = (float*)d_out;

    float *pWcat, *pP, *pCat, *pPart;
    cudaGetSymbolAddress((void**)&pWcat, g_Wcat);
    cudaGetSymbolAddress((void**)&pP,    g_P);
    cudaGetSymbolAddress((void**)&pCat,  g_cat);
    cudaGetSymbolAddress((void**)&pPart, g_part);

    concat_w<<<(MPROJ * CSd + 255) / 256, 256>>>(Wq, Wk, Wv, Wqp, Wkp, Wvp);
    gemm64<<<dim3(NN / 64, MPROJ / 64, 1), 256>>>(pWcat, s, pP, MPROJ, NN, CSd);
    prep_kernel<<<(Hd * NN + 255) / 256, 256>>>(t_r, t_t, gam);
    qk_gemm<<<dim3(NN / 64, NN / 64, Hd), 256>>>();
    bias_kernel<<<dim3(256, 2), 256>>>(z, Wb);
    logits2<<<NN, 256>>>();
    o1k<<<dim3(NN, 2), 256>>>(z);
    o23k<<<NN, 256>>>();
    o3fix2<<<NN / 8, 256>>>(t_r, t_t);
    gemm64<<<dim3(NN / 64, CSd / 64, KSPLIT), 256>>>(Ws, pCat, pPart, CSd, NN, CATd);
    reduce_out<<<(CSd * NN + 255) / 256, 256>>>(bs, out);
}